// round 15
// baseline (speedup 1.0000x reference)
#include <cuda_runtime.h>
#include <math_constants.h>
#include <cstdint>

#define Bn 8
#define Cc 512
#define Nn 1024
#define NH 8
#define HD 64

// ---------------- scratch (device globals; no allocation) ----------------
__device__ uint32_t g_xb [Bn * 262144];      // 8 MB  bf16 b-frag (x_norm)
__device__ uint32_t g_atb[Bn * 262144];      // 8 MB  bf16 b-frag (attn out)
__device__ uint32_t g_wA [96 * 32 * 128];    // 1.5 MB a-frag (w_qkv)
__device__ uint32_t g_wP [32 * 32 * 128];    // 0.5 MB a-frag (w_proj)
__device__ uint32_t g_qa [Bn * NH * 32768];  // 8 MB Q a-frag (pre-scaled)
__device__ uint32_t g_kb [Bn * NH * 32768];  // 8 MB K b-frag
__device__ uint32_t g_vb [Bn * NH * 32768];  // 8 MB V b-frag

// ---------------- helpers ----------------
__device__ __forceinline__ uint32_t pack2(float lo, float hi) {
    uint32_t r;
    asm("cvt.rn.bf16x2.f32 %0, %1, %2;" : "=r"(r) : "f"(hi), "f"(lo));
    return r;
}
__device__ __forceinline__ void mma_bf16(float* d, const uint32_t* a, const uint32_t* b) {
    asm volatile(
        "mma.sync.aligned.m16n8k16.row.col.f32.bf16.bf16.f32 "
        "{%0,%1,%2,%3}, {%4,%5,%6,%7}, {%8,%9}, {%0,%1,%2,%3};"
        : "+f"(d[0]), "+f"(d[1]), "+f"(d[2]), "+f"(d[3])
        : "r"(a[0]), "r"(a[1]), "r"(a[2]), "r"(a[3]), "r"(b[0]), "r"(b[1]));
}
__device__ __forceinline__ float fexp2(float t) {
    float r;
    asm("ex2.approx.ftz.f32 %0, %1;" : "=f"(r) : "f"(t));
    return r;
}
__device__ __forceinline__ uint32_t smem_u32(const void* p) {
    uint32_t a;
    asm("{ .reg .u64 t; cvta.to.shared.u64 t, %1; cvt.u32.u64 %0, t; }" : "=r"(a) : "l"(p));
    return a;
}
__device__ __forceinline__ void cp16(uint32_t saddr, const void* g) {
    asm volatile("cp.async.cg.shared.global [%0], [%1], 16;" :: "r"(saddr), "l"(g));
}
#define CP_COMMIT() asm volatile("cp.async.commit_group;")
#define CP_WAIT(n)  asm volatile("cp.async.wait_group %0;" :: "n"(n))

#define QSCL 0.1803368801111204f   /* 0.125 * log2(e) */

// ---------------- merged prep: wprep(w_qkv) + wprep(w_proj) + GroupNorm ----------------
__device__ __forceinline__ void wprep_body(const float* __restrict__ W,
                                           uint32_t* __restrict__ dst, int e) {
    int reg = e & 3, lane = (e >> 2) & 31, ks = (e >> 7) & 31, mtile = e >> 12;
    int r = lane >> 2, t = lane & 3;
    int o  = mtile * 16 + r + (reg & 1) * 8;
    int c0 = ks * 16 + 2 * t + (reg & 2) * 4;
    dst[e] = pack2(W[o * 512 + c0], W[o * 512 + c0 + 1]);
}

__global__ void prep_kernel(const float* __restrict__ w_qkv,
                            const float* __restrict__ w_proj,
                            const float* __restrict__ x,
                            const float* __restrict__ gamma,
                            const float* __restrict__ beta) {
    int blk = blockIdx.x;
    int tid = threadIdx.x;
    if (blk < 1536) { wprep_body(w_qkv, g_wA, blk * 256 + tid); return; }
    if (blk < 2048) { wprep_body(w_proj, g_wP, (blk - 1536) * 256 + tid); return; }

    // ---- GroupNorm block ----
    extern __shared__ float sx[];   // [16][1024]
    int gi = blk - 2048;
    int b = gi >> 5;
    int g = gi & 31;
    const float* xp = x + ((size_t)b * Cc + g * 16) * Nn;

    float s = 0.f, s2 = 0.f;
    for (int i = tid * 4; i < 16384; i += 1024) {
        float4 v = *(const float4*)(xp + i);
        *(float4*)(sx + i) = v;
        s  += v.x + v.y + v.z + v.w;
        s2 += v.x * v.x + v.y * v.y + v.z * v.z + v.w * v.w;
    }
    for (int off = 16; off; off >>= 1) {
        s  += __shfl_xor_sync(0xffffffffu, s,  off);
        s2 += __shfl_xor_sync(0xffffffffu, s2, off);
    }
    __shared__ float sh[2][8];
    int w = tid >> 5;
    if ((tid & 31) == 0) { sh[0][w] = s; sh[1][w] = s2; }
    __syncthreads();
    if (tid < 32) {
        s  = (tid < 8) ? sh[0][tid] : 0.f;
        s2 = (tid < 8) ? sh[1][tid] : 0.f;
        for (int off = 4; off; off >>= 1) {
            s  += __shfl_xor_sync(0xffffffffu, s,  off);
            s2 += __shfl_xor_sync(0xffffffffu, s2, off);
        }
        if (tid == 0) { sh[0][0] = s; sh[1][0] = s2; }
    }
    __syncthreads();
    float mean = sh[0][0] * (1.f / 16384.f);
    float var  = sh[1][0] * (1.f / 16384.f) - mean * mean;
    float rstd = rsqrtf(var + 1e-5f);

    float ga[16], be[16];
    #pragma unroll
    for (int c = 0; c < 16; ++c) {
        float gg = __ldg(gamma + g * 16 + c) * rstd;
        ga[c] = gg;
        be[c] = __ldg(beta + g * 16 + c) - mean * gg;
    }

    uint32_t* op = g_xb + ((size_t)b * 32 + g) * 8192;
    #pragma unroll
    for (int rr = 0; rr < 4; ++rr) {
        int n = tid + rr * 256;
        float v[16];
        #pragma unroll
        for (int lc = 0; lc < 16; ++lc) v[lc] = sx[lc * 1024 + n] * ga[lc] + be[lc];
        uint4 A = make_uint4(pack2(v[0], v[1]), pack2(v[8],  v[9]),
                             pack2(v[2], v[3]), pack2(v[10], v[11]));
        uint4 B = make_uint4(pack2(v[4], v[5]), pack2(v[12], v[13]),
                             pack2(v[6], v[7]), pack2(v[14], v[15]));
        *(uint4*)(op + (size_t)n * 8)     = A;
        *(uint4*)(op + (size_t)n * 8 + 4) = B;
    }
}

// ---------------- bf16 mma GEMM: 4-stage x 2-kstep cp.async pipeline ----------------
__global__ __launch_bounds__(256, 2) void gemm_mma(
    const uint32_t* __restrict__ Amat, const uint32_t* __restrict__ Bmat,
    const float* __restrict__ bias, const float* __restrict__ resid,
    float* __restrict__ out, int M, int qkvmode)
{
    extern __shared__ uint32_t bsm[];   // 4 stages x 2048 words = 32 KB
    const int tid = threadIdx.x;
    const int lane = tid & 31;
    const int wid = tid >> 5;
    const int wm = wid & 3;
    const int wn = wid >> 2;
    const int nb = blockIdx.x * 128;
    const int ob = blockIdx.y * 128;
    const int b  = blockIdx.z;
    const int r = lane >> 2, c = lane & 3;

    const uint32_t* Aw = Amat + (size_t)((ob >> 4) + wm * 2) * 4096 + lane * 4;
    const uint32_t* Bg = Bmat + (size_t)b * 262144 + (size_t)nb * 8 + tid * 4;
    const uint32_t sb = smem_u32(bsm);
    const uint32_t* bwarp = bsm + wn * 512 + r * 8 + c * 2;

    float acc[2][8][4];
    #pragma unroll
    for (int mt = 0; mt < 2; ++mt)
        #pragma unroll
        for (int nt = 0; nt < 8; ++nt)
            #pragma unroll
            for (int q = 0; q < 4; ++q) acc[mt][nt][q] = 0.f;

    uint4 afr[4][2];
    auto lda = [&](int ks) {
        afr[ks & 3][0] = *(const uint4*)(Aw + ks * 128);
        afr[ks & 3][1] = *(const uint4*)(Aw + 4096 + ks * 128);
    };
    auto bstage = [&](int s) {   // stage s covers k-steps 2s, 2s+1
        uint32_t dst = sb + (((s & 3) << 11) + tid * 4) * 4;
        cp16(dst,        Bg + (size_t)(2 * s) * 8192);
        cp16(dst + 4096, Bg + (size_t)(2 * s + 1) * 8192);
        CP_COMMIT();
    };

    bstage(0); bstage(1); bstage(2);
    lda(0); lda(1); lda(2); lda(3);
    CP_WAIT(2);
    __syncthreads();

    #pragma unroll 2
    for (int s = 0; s < 16; ++s) {
        #pragma unroll
        for (int kk = 0; kk < 2; ++kk) {
            const int ks = 2 * s + kk;
            uint2 bfr[8];
            #pragma unroll
            for (int nt = 0; nt < 8; ++nt)
                bfr[nt] = *(const uint2*)(bwarp + ((s & 3) << 11) + (kk << 10) + nt * 64);
            #pragma unroll
            for (int mt = 0; mt < 2; ++mt)
                #pragma unroll
                for (int nt = 0; nt < 8; ++nt)
                    mma_bf16(acc[mt][nt], (const uint32_t*)&afr[ks & 3][mt],
                             (const uint32_t*)&bfr[nt]);
            if (s + 2 < 16) lda(2 * s + 4 + kk);
        }
        if (s + 3 < 16) bstage(s + 3);
        else CP_COMMIT();
        CP_WAIT(2);
        __syncthreads();
    }

    if (qkvmode) {
        #pragma unroll
        for (int mt = 0; mt < 2; ++mt) {
            int o0 = ob + wm * 32 + mt * 16 + r;
            float b0 = __ldg(bias + o0);
            float b1 = __ldg(bias + o0 + 8);
            #pragma unroll
            for (int nt = 0; nt < 8; ++nt) {
                int n = nb + wn * 64 + nt * 8 + 2 * c;
                float v0 = acc[mt][nt][0] + b0, v1 = acc[mt][nt][1] + b0;
                float v2 = acc[mt][nt][2] + b1, v3 = acc[mt][nt][3] + b1;
                if (o0 < 1024) {   // Q or K: pairs along d -> butterfly
                    if (o0 < 512) { v0 *= QSCL; v1 *= QSCL; v2 *= QSCL; v3 *= QSCL; }
                    float u0 = __shfl_xor_sync(0xffffffffu, v0, 4);
                    float u1 = __shfl_xor_sync(0xffffffffu, v1, 4);
                    float u2 = __shfl_xor_sync(0xffffffffu, v2, 4);
                    float u3 = __shfl_xor_sync(0xffffffffu, v3, 4);
                    if (!(r & 1)) {
                        uint32_t w0 = pack2(v0, u0), w1 = pack2(v1, u1);
                        uint32_t w2 = pack2(v2, u2), w3 = pack2(v3, u3);
                        if (o0 < 512) {        // Q a-frag
                            int h = o0 >> 6, d0 = o0 & 63, q = n;
                            int qt = q >> 4, q_in = q & 15;
                            int ksd = d0 >> 4, tp = (d0 & 15) >> 1;
                            int lane0 = (q_in & 7) * 4 + tp;
                            int rb = (q_in >> 3) & 1;
                            uint32_t* dst = g_qa
                                + ((size_t)((b * 8 + h) * 64 + qt) * 4 + ksd) * 128;
                            dst[lane0 * 4 + rb]           = w0;
                            dst[(lane0 + 4) * 4 + rb]     = w1;
                            dst[lane0 * 4 + rb + 2]       = w2;
                            dst[(lane0 + 4) * 4 + rb + 2] = w3;
                        } else {               // K b-frag
                            int oh = o0 - 512;
                            int h = oh >> 6, d0 = oh & 63, m = n;
                            int kt = m >> 6, m_in = m & 63;
                            int ksd = d0 >> 4, t = (d0 & 15) >> 1;
                            uint32_t* dst = g_kb
                                + ((size_t)((b * 8 + h) * 16 + kt) * 4 + ksd) * 512;
                            dst[m_in * 8 + t * 2]           = w0;
                            dst[(m_in + 1) * 8 + t * 2]     = w1;
                            dst[m_in * 8 + t * 2 + 1]       = w2;
                            dst[(m_in + 1) * 8 + t * 2 + 1] = w3;
                        }
                    }
                } else {           // V: pairs along m -> in-thread
                    int oh = o0 - 1024;
                    int h = oh >> 6, d = oh & 63, m = n;
                    int kt = m >> 6;
                    int ksm = nt >> 1;
                    int tr = c * 2 + (nt & 1);
                    uint32_t w0 = pack2(v0, v1);
                    uint32_t w1 = pack2(v2, v3);
                    uint32_t* dst = g_vb
                        + ((size_t)((b * 8 + h) * 16 + kt) * 4 + ksm) * 512;
                    dst[d * 8 + tr]       = w0;
                    dst[(d + 8) * 8 + tr] = w1;
                }
            }
        }
    } else {
        #pragma unroll
        for (int mt = 0; mt < 2; ++mt) {
            int o = ob + wm * 32 + mt * 16 + r;
            float b0 = __ldg(bias + o);
            float b1 = __ldg(bias + o + 8);
            #pragma unroll
            for (int nt = 0; nt < 8; ++nt) {
                int n = nb + wn * 64 + nt * 8 + 2 * c;
                size_t i0 = ((size_t)b * M + o) * Nn + n;
                size_t i1 = i0 + (size_t)8 * Nn;
                float2 v0 = make_float2(acc[mt][nt][0] + b0, acc[mt][nt][1] + b0);
                float2 v1 = make_float2(acc[mt][nt][2] + b1, acc[mt][nt][3] + b1);
                if (resid) {
                    float2 r0 = *(const float2*)(resid + i0);
                    float2 r1 = *(const float2*)(resid + i1);
                    v0.x += r0.x; v0.y += r0.y;
                    v1.x += r1.x; v1.y += r1.y;
                }
                *(float2*)(out + i0) = v0;
                *(float2*)(out + i1) = v1;
            }
        }
    }
}

// ---------------- flash attention: 2 q-tiles per warp, K/V frags reused x2 ----------------
// block = 256 q (16 qtiles), warp w owns qtiles 2w, 2w+1. Max-free softmax, 3-stage ring.
// smem words: kbuf[3] @0..6143, vbuf[3] @6144..12287; epilogue reuses 0..8447 as 64x132 f32.
__global__ __launch_bounds__(256) void attn_mma() {
    const int b = blockIdx.z, h = blockIdx.y;
    const uint32_t* qa = g_qa + (size_t)(b * 8 + h) * 32768;
    const uint32_t* kb = g_kb + (size_t)(b * 8 + h) * 32768;
    const uint32_t* vb = g_vb + (size_t)(b * 8 + h) * 32768;

    extern __shared__ uint32_t smu[];
    const int tid = threadIdx.x, lane = tid & 31, w = tid >> 5;
    const int r = lane >> 2, c = lane & 3;
    const uint32_t sbase = smem_u32(smu);

    // Q a-frags for 2 qtiles
    uint4 aq0[4], aq1[4];
    {
        const uint32_t* qp = qa + (size_t)(blockIdx.x * 16 + 2 * w) * 512 + lane * 4;
        #pragma unroll
        for (int ks = 0; ks < 4; ++ks) {
            aq0[ks] = *(const uint4*)(qp + ks * 128);
            aq1[ks] = *(const uint4*)(qp + 512 + ks * 128);
        }
    }

    auto stage = [&](int kt) {
        int buf = kt % 3;
        const uint32_t* kg = kb + (size_t)kt * 2048 + tid * 8;
        const uint32_t* vg = vb + (size_t)kt * 2048 + tid * 8;
        uint32_t ksm = sbase + (buf * 2048 + tid * 8) * 4;
        uint32_t vsm = sbase + (6144 + buf * 2048 + tid * 8) * 4;
        cp16(ksm,      kg);
        cp16(ksm + 16, kg + 4);
        cp16(vsm,      vg);
        cp16(vsm + 16, vg + 4);
        CP_COMMIT();
    };

    float oacc0[8][4], oacc1[8][4];
    #pragma unroll
    for (int j = 0; j < 8; ++j)
        #pragma unroll
        for (int i = 0; i < 4; ++i) { oacc0[j][i] = 0.f; oacc1[j][i] = 0.f; }
    float rs00 = 0.f, rs01 = 0.f, rs10 = 0.f, rs11 = 0.f;

    stage(0);
    stage(1);
    CP_WAIT(1);
    __syncthreads();

    for (int kt = 0; kt < 16; ++kt) {
        if (kt + 2 < 16) stage(kt + 2);

        const uint32_t* ksb = smu + (kt % 3) * 2048;
        const uint32_t* vsb = smu + 6144 + (kt % 3) * 2048;

        // S = Q K^T for both qtiles, each K frag loaded once
        float s0[8][4], s1[8][4];
        #pragma unroll
        for (int j = 0; j < 8; ++j)
            #pragma unroll
            for (int i = 0; i < 4; ++i) { s0[j][i] = 0.f; s1[j][i] = 0.f; }
        #pragma unroll
        for (int ks = 0; ks < 4; ++ks) {
            uint2 bk[8];
            #pragma unroll
            for (int j = 0; j < 8; ++j)
                bk[j] = *(const uint2*)(ksb + ks * 512 + (j * 8 + r) * 8 + c * 2);
            #pragma unroll
            for (int j = 0; j < 8; ++j) {
                mma_bf16(s0[j], (const uint32_t*)&aq0[ks], (const uint32_t*)&bk[j]);
                mma_bf16(s1[j], (const uint32_t*)&aq1[ks], (const uint32_t*)&bk[j]);
            }
        }

        // max-free softmax: P = exp2(S)
        uint4 pa0[4], pa1[4];
        #pragma unroll
        for (int t = 0; t < 4; ++t) {
            float e0 = fexp2(s0[2*t][0]),   e1 = fexp2(s0[2*t][1]);
            float e2 = fexp2(s0[2*t][2]),   e3 = fexp2(s0[2*t][3]);
            float f0 = fexp2(s0[2*t+1][0]), f1 = fexp2(s0[2*t+1][1]);
            float f2 = fexp2(s0[2*t+1][2]), f3 = fexp2(s0[2*t+1][3]);
            rs00 += e0 + e1 + f0 + f1;
            rs01 += e2 + e3 + f2 + f3;
            pa0[t] = make_uint4(pack2(e0, e1), pack2(e2, e3),
                                pack2(f0, f1), pack2(f2, f3));
            float g0 = fexp2(s1[2*t][0]),   g1 = fexp2(s1[2*t][1]);
            float g2 = fexp2(s1[2*t][2]),   g3 = fexp2(s1[2*t][3]);
            float h0 = fexp2(s1[2*t+1][0]), h1 = fexp2(s1[2*t+1][1]);
            float h2 = fexp2(s1[2*t+1][2]), h3 = fexp2(s1[2*t+1][3]);
            rs10 += g0 + g1 + h0 + h1;
            rs11 += g2 + g3 + h2 + h3;
            pa1[t] = make_uint4(pack2(g0, g1), pack2(g2, g3),
                                pack2(h0, h1), pack2(h2, h3));
        }

        // O += P V for both qtiles, each V frag loaded once
        #pragma unroll
        for (int ks = 0; ks < 4; ++ks) {
            #pragma unroll
            for (int j = 0; j < 8; ++j) {
                uint2 bv = *(const uint2*)(vsb + ks * 512 + (j * 8 + r) * 8 + c * 2);
                mma_bf16(oacc0[j], (const uint32_t*)&pa0[ks], (const uint32_t*)&bv);
                mma_bf16(oacc1[j], (const uint32_t*)&pa1[ks], (const uint32_t*)&bv);
            }
        }

        CP_WAIT(1);
        __syncthreads();
    }

    // quad-reduce sums, two-pass transpose+store (128 q per pass, 64x132 f32 buffer)
    rs00 += __shfl_xor_sync(0xffffffffu, rs00, 1);
    rs00 += __shfl_xor_sync(0xffffffffu, rs00, 2);
    rs01 += __shfl_xor_sync(0xffffffffu, rs01, 1);
    rs01 += __shfl_xor_sync(0xffffffffu, rs01, 2);
    rs10 += __shfl_xor_sync(0xffffffffu, rs10, 1);
    rs10 += __shfl_xor_sync(0xffffffffu, rs10, 2);
    rs11 += __shfl_xor_sync(0xffffffffu, rs11, 1);
    rs11 += __shfl_xor_sync(0xffffffffu, rs11, 2);
    float i00 = 1.f / rs00, i01 = 1.f / rs01;
    float i10 = 1.f / rs10, i11 = 1.f / rs11;

    float* os = (float*)smu;   // 64 x 132 floats = 8448 words
    #pragma unroll
    for (int p = 0; p < 2; ++p) {
        if ((w >> 2) == p) {
            int qL = (w & 3) * 32 + r;
            #pragma unroll
            for (int j = 0; j < 8; ++j) {
                int d = j * 8 + 2 * c;
                os[d * 132 + qL]            = oacc0[j][0] * i00;
                os[(d + 1) * 132 + qL]      = oacc0[j][1] * i00;
                os[d * 132 + qL + 8]        = oacc0[j][2] * i01;
                os[(d + 1) * 132 + qL + 8]  = oacc0[j][3] * i01;
                os[d * 132 + qL + 16]       = oacc1[j][0] * i10;
                os[(d + 1) * 132 + qL + 16] = oacc1[j][1] * i10;
                os[d * 132 + qL + 24]       = oacc1[j][2] * i11;
                os[(d + 1) * 132 + qL + 24] = oacc1[j][3] * i11;
            }
        }
        __syncthreads();
        const int qbase = blockIdx.x * 256 + p * 128;
        #pragma unroll
        for (int rr = 0; rr < 8; ++rr) {
            int f = tid + rr * 256;
            int t = f & 3, nl = (f >> 2) & 127, ksl = f >> 9;
            int c0 = ksl * 16 + 2 * t;
            uint2 wv;
            wv.x = pack2(os[c0 * 132 + nl],       os[(c0 + 1) * 132 + nl]);
            wv.y = pack2(os[(c0 + 8) * 132 + nl], os[(c0 + 9) * 132 + nl]);
            *(uint2*)(g_atb + ((size_t)b * 32 + h * 4 + ksl) * 8192
                      + (size_t)(qbase + nl) * 8 + t * 2) = wv;
        }
        __syncthreads();
    }
}

// ---------------- launch ----------------
extern "C" void kernel_launch(void* const* d_in, const int* in_sizes, int n_in,
                              void* d_out, int out_size) {
    const float* x      = (const float*)d_in[0];
    const float* gamma  = (const float*)d_in[1];
    const float* beta   = (const float*)d_in[2];
    const float* w_qkv  = (const float*)d_in[3];
    const float* b_qkv  = (const float*)d_in[4];
    const float* w_proj = (const float*)d_in[5];
    const float* b_proj = (const float*)d_in[6];
    float* out = (float*)d_out;

    uint32_t *xb, *atb, *wA, *wP;
    cudaGetSymbolAddress((void**)&xb,  g_xb);
    cudaGetSymbolAddress((void**)&atb, g_atb);
    cudaGetSymbolAddress((void**)&wA,  g_wA);
    cudaGetSymbolAddress((void**)&wP,  g_wP);

    const int prep_smem = 16 * 1024 * sizeof(float);   // 64 KB (gn blocks)
    const int gemm_smem = 32768;                       // 4 stages x 8 KB
    const int attn_smem = 12288 * 4;                   // 49152 B (3-stage ring)
    cudaFuncSetAttribute(prep_kernel, cudaFuncAttributeMaxDynamicSharedMemorySize, prep_smem);
    cudaFuncSetAttribute(gemm_mma,    cudaFuncAttributeMaxDynamicSharedMemorySize, gemm_smem);
    cudaFuncSetAttribute(attn_mma,    cudaFuncAttributeMaxDynamicSharedMemorySize, attn_smem);

    prep_kernel<<<2304, 256, prep_smem>>>(w_qkv, w_proj, x, gamma, beta);
    gemm_mma<<<dim3(8, 12, 8), 256, gemm_smem>>>(wA, xb, b_qkv, nullptr, nullptr, 0, 1);
    attn_mma<<<dim3(4, NH, Bn), 256, attn_smem>>>();
    gemm_mma<<<dim3(8, 4, 8), 256, gemm_smem>>>(wP, atb, b_proj, x, out, Cc, 0);
}

// round 16
// speedup vs baseline: 1.4895x; 1.4895x over previous
#include <cuda_runtime.h>
#include <math_constants.h>
#include <cstdint>

#define Bn 8
#define Cc 512
#define Nn 1024
#define NH 8
#define HD 64

// ---------------- scratch (device globals; no allocation) ----------------
__device__ uint32_t g_xb [Bn * 262144];      // 8 MB  bf16 b-frag (x_norm)
__device__ uint32_t g_atb[Bn * 262144];      // 8 MB  bf16 b-frag (attn out)
__device__ uint32_t g_wA [96 * 32 * 128];    // 1.5 MB a-frag (w_qkv)
__device__ uint32_t g_wP [32 * 32 * 128];    // 0.5 MB a-frag (w_proj)
__device__ uint32_t g_qa [Bn * NH * 32768];  // 8 MB Q a-frag (pre-scaled)
__device__ uint32_t g_kb [Bn * NH * 32768];  // 8 MB K b-frag
__device__ uint32_t g_vb [Bn * NH * 32768];  // 8 MB V b-frag

// ---------------- helpers ----------------
__device__ __forceinline__ uint32_t pack2(float lo, float hi) {
    uint32_t r;
    asm("cvt.rn.bf16x2.f32 %0, %1, %2;" : "=r"(r) : "f"(hi), "f"(lo));
    return r;
}
__device__ __forceinline__ void mma_bf16(float* d, const uint32_t* a, const uint32_t* b) {
    asm volatile(
        "mma.sync.aligned.m16n8k16.row.col.f32.bf16.bf16.f32 "
        "{%0,%1,%2,%3}, {%4,%5,%6,%7}, {%8,%9}, {%0,%1,%2,%3};"
        : "+f"(d[0]), "+f"(d[1]), "+f"(d[2]), "+f"(d[3])
        : "r"(a[0]), "r"(a[1]), "r"(a[2]), "r"(a[3]), "r"(b[0]), "r"(b[1]));
}
__device__ __forceinline__ float fexp2(float t) {
    float r;
    asm("ex2.approx.ftz.f32 %0, %1;" : "=f"(r) : "f"(t));
    return r;
}
__device__ __forceinline__ uint32_t smem_u32(const void* p) {
    uint32_t a;
    asm("{ .reg .u64 t; cvta.to.shared.u64 t, %1; cvt.u32.u64 %0, t; }" : "=r"(a) : "l"(p));
    return a;
}
__device__ __forceinline__ void cp16(uint32_t saddr, const void* g) {
    asm volatile("cp.async.cg.shared.global [%0], [%1], 16;" :: "r"(saddr), "l"(g));
}
#define CP_COMMIT() asm volatile("cp.async.commit_group;")
#define CP_WAIT(n)  asm volatile("cp.async.wait_group %0;" :: "n"(n))

#define QSCL 0.1803368801111204f   /* 0.125 * log2(e) */

// ---------------- merged prep: wprep(w_qkv) + wprep(w_proj) + GroupNorm ----------------
__device__ __forceinline__ void wprep_body(const float* __restrict__ W,
                                           uint32_t* __restrict__ dst, int e) {
    int reg = e & 3, lane = (e >> 2) & 31, ks = (e >> 7) & 31, mtile = e >> 12;
    int r = lane >> 2, t = lane & 3;
    int o  = mtile * 16 + r + (reg & 1) * 8;
    int c0 = ks * 16 + 2 * t + (reg & 2) * 4;
    dst[e] = pack2(W[o * 512 + c0], W[o * 512 + c0 + 1]);
}

__global__ void prep_kernel(const float* __restrict__ w_qkv,
                            const float* __restrict__ w_proj,
                            const float* __restrict__ x,
                            const float* __restrict__ gamma,
                            const float* __restrict__ beta) {
    int blk = blockIdx.x;
    int tid = threadIdx.x;
    if (blk < 1536) { wprep_body(w_qkv, g_wA, blk * 256 + tid); return; }
    if (blk < 2048) { wprep_body(w_proj, g_wP, (blk - 1536) * 256 + tid); return; }

    // ---- GroupNorm block ----
    extern __shared__ float sx[];   // [16][1024]
    int gi = blk - 2048;
    int b = gi >> 5;
    int g = gi & 31;
    const float* xp = x + ((size_t)b * Cc + g * 16) * Nn;

    float s = 0.f, s2 = 0.f;
    for (int i = tid * 4; i < 16384; i += 1024) {
        float4 v = *(const float4*)(xp + i);
        *(float4*)(sx + i) = v;
        s  += v.x + v.y + v.z + v.w;
        s2 += v.x * v.x + v.y * v.y + v.z * v.z + v.w * v.w;
    }
    for (int off = 16; off; off >>= 1) {
        s  += __shfl_xor_sync(0xffffffffu, s,  off);
        s2 += __shfl_xor_sync(0xffffffffu, s2, off);
    }
    __shared__ float sh[2][8];
    int w = tid >> 5;
    if ((tid & 31) == 0) { sh[0][w] = s; sh[1][w] = s2; }
    __syncthreads();
    if (tid < 32) {
        s  = (tid < 8) ? sh[0][tid] : 0.f;
        s2 = (tid < 8) ? sh[1][tid] : 0.f;
        for (int off = 4; off; off >>= 1) {
            s  += __shfl_xor_sync(0xffffffffu, s,  off);
            s2 += __shfl_xor_sync(0xffffffffu, s2, off);
        }
        if (tid == 0) { sh[0][0] = s; sh[1][0] = s2; }
    }
    __syncthreads();
    float mean = sh[0][0] * (1.f / 16384.f);
    float var  = sh[1][0] * (1.f / 16384.f) - mean * mean;
    float rstd = rsqrtf(var + 1e-5f);

    float ga[16], be[16];
    #pragma unroll
    for (int c = 0; c < 16; ++c) {
        float gg = __ldg(gamma + g * 16 + c) * rstd;
        ga[c] = gg;
        be[c] = __ldg(beta + g * 16 + c) - mean * gg;
    }

    uint32_t* op = g_xb + ((size_t)b * 32 + g) * 8192;
    #pragma unroll
    for (int rr = 0; rr < 4; ++rr) {
        int n = tid + rr * 256;
        float v[16];
        #pragma unroll
        for (int lc = 0; lc < 16; ++lc) v[lc] = sx[lc * 1024 + n] * ga[lc] + be[lc];
        uint4 A = make_uint4(pack2(v[0], v[1]), pack2(v[8],  v[9]),
                             pack2(v[2], v[3]), pack2(v[10], v[11]));
        uint4 B = make_uint4(pack2(v[4], v[5]), pack2(v[12], v[13]),
                             pack2(v[6], v[7]), pack2(v[14], v[15]));
        *(uint4*)(op + (size_t)n * 8)     = A;
        *(uint4*)(op + (size_t)n * 8 + 4) = B;
    }
}

// ---------------- bf16 mma GEMM: 4-stage x 2-kstep cp.async pipeline ----------------
__global__ __launch_bounds__(256, 2) void gemm_mma(
    const uint32_t* __restrict__ Amat, const uint32_t* __restrict__ Bmat,
    const float* __restrict__ bias, const float* __restrict__ resid,
    float* __restrict__ out, int M, int qkvmode)
{
    extern __shared__ uint32_t bsm[];   // 4 stages x 2048 words = 32 KB
    const int tid = threadIdx.x;
    const int lane = tid & 31;
    const int wid = tid >> 5;
    const int wm = wid & 3;
    const int wn = wid >> 2;
    const int nb = blockIdx.x * 128;
    const int ob = blockIdx.y * 128;
    const int b  = blockIdx.z;
    const int r = lane >> 2, c = lane & 3;

    const uint32_t* Aw = Amat + (size_t)((ob >> 4) + wm * 2) * 4096 + lane * 4;
    const uint32_t* Bg = Bmat + (size_t)b * 262144 + (size_t)nb * 8 + tid * 4;
    const uint32_t sb = smem_u32(bsm);
    const uint32_t* bwarp = bsm + wn * 512 + r * 8 + c * 2;

    float acc[2][8][4];
    #pragma unroll
    for (int mt = 0; mt < 2; ++mt)
        #pragma unroll
        for (int nt = 0; nt < 8; ++nt)
            #pragma unroll
            for (int q = 0; q < 4; ++q) acc[mt][nt][q] = 0.f;

    uint4 afr[4][2];
    auto lda = [&](int ks) {
        afr[ks & 3][0] = *(const uint4*)(Aw + ks * 128);
        afr[ks & 3][1] = *(const uint4*)(Aw + 4096 + ks * 128);
    };
    auto bstage = [&](int s) {   // stage s covers k-steps 2s, 2s+1
        uint32_t dst = sb + (((s & 3) << 11) + tid * 4) * 4;
        cp16(dst,        Bg + (size_t)(2 * s) * 8192);
        cp16(dst + 4096, Bg + (size_t)(2 * s + 1) * 8192);
        CP_COMMIT();
    };

    bstage(0); bstage(1); bstage(2);
    lda(0); lda(1); lda(2); lda(3);
    CP_WAIT(2);
    __syncthreads();

    #pragma unroll 2
    for (int s = 0; s < 16; ++s) {
        #pragma unroll
        for (int kk = 0; kk < 2; ++kk) {
            const int ks = 2 * s + kk;
            uint2 bfr[8];
            #pragma unroll
            for (int nt = 0; nt < 8; ++nt)
                bfr[nt] = *(const uint2*)(bwarp + ((s & 3) << 11) + (kk << 10) + nt * 64);
            #pragma unroll
            for (int mt = 0; mt < 2; ++mt)
                #pragma unroll
                for (int nt = 0; nt < 8; ++nt)
                    mma_bf16(acc[mt][nt], (const uint32_t*)&afr[ks & 3][mt],
                             (const uint32_t*)&bfr[nt]);
            if (s + 2 < 16) lda(2 * s + 4 + kk);
        }
        if (s + 3 < 16) bstage(s + 3);
        else CP_COMMIT();
        CP_WAIT(2);
        __syncthreads();
    }

    if (qkvmode) {
        #pragma unroll
        for (int mt = 0; mt < 2; ++mt) {
            int o0 = ob + wm * 32 + mt * 16 + r;
            float b0 = __ldg(bias + o0);
            float b1 = __ldg(bias + o0 + 8);
            #pragma unroll
            for (int nt = 0; nt < 8; ++nt) {
                int n = nb + wn * 64 + nt * 8 + 2 * c;
                float v0 = acc[mt][nt][0] + b0, v1 = acc[mt][nt][1] + b0;
                float v2 = acc[mt][nt][2] + b1, v3 = acc[mt][nt][3] + b1;
                if (o0 < 1024) {   // Q or K: pairs along d -> butterfly
                    if (o0 < 512) { v0 *= QSCL; v1 *= QSCL; v2 *= QSCL; v3 *= QSCL; }
                    float u0 = __shfl_xor_sync(0xffffffffu, v0, 4);
                    float u1 = __shfl_xor_sync(0xffffffffu, v1, 4);
                    float u2 = __shfl_xor_sync(0xffffffffu, v2, 4);
                    float u3 = __shfl_xor_sync(0xffffffffu, v3, 4);
                    if (!(r & 1)) {
                        uint32_t w0 = pack2(v0, u0), w1 = pack2(v1, u1);
                        uint32_t w2 = pack2(v2, u2), w3 = pack2(v3, u3);
                        if (o0 < 512) {        // Q a-frag
                            int h = o0 >> 6, d0 = o0 & 63, q = n;
                            int qt = q >> 4, q_in = q & 15;
                            int ksd = d0 >> 4, tp = (d0 & 15) >> 1;
                            int lane0 = (q_in & 7) * 4 + tp;
                            int rb = (q_in >> 3) & 1;
                            uint32_t* dst = g_qa
                                + ((size_t)((b * 8 + h) * 64 + qt) * 4 + ksd) * 128;
                            dst[lane0 * 4 + rb]           = w0;
                            dst[(lane0 + 4) * 4 + rb]     = w1;
                            dst[lane0 * 4 + rb + 2]       = w2;
                            dst[(lane0 + 4) * 4 + rb + 2] = w3;
                        } else {               // K b-frag
                            int oh = o0 - 512;
                            int h = oh >> 6, d0 = oh & 63, m = n;
                            int kt = m >> 6, m_in = m & 63;
                            int ksd = d0 >> 4, t = (d0 & 15) >> 1;
                            uint32_t* dst = g_kb
                                + ((size_t)((b * 8 + h) * 16 + kt) * 4 + ksd) * 512;
                            dst[m_in * 8 + t * 2]           = w0;
                            dst[(m_in + 1) * 8 + t * 2]     = w1;
                            dst[m_in * 8 + t * 2 + 1]       = w2;
                            dst[(m_in + 1) * 8 + t * 2 + 1] = w3;
                        }
                    }
                } else {           // V: pairs along m -> in-thread
                    int oh = o0 - 1024;
                    int h = oh >> 6, d = oh & 63, m = n;
                    int kt = m >> 6;
                    int ksm = nt >> 1;
                    int tr = c * 2 + (nt & 1);
                    uint32_t w0 = pack2(v0, v1);
                    uint32_t w1 = pack2(v2, v3);
                    uint32_t* dst = g_vb
                        + ((size_t)((b * 8 + h) * 16 + kt) * 4 + ksm) * 512;
                    dst[d * 8 + tr]       = w0;
                    dst[(d + 8) * 8 + tr] = w1;
                }
            }
        }
    } else {
        #pragma unroll
        for (int mt = 0; mt < 2; ++mt) {
            int o = ob + wm * 32 + mt * 16 + r;
            float b0 = __ldg(bias + o);
            float b1 = __ldg(bias + o + 8);
            #pragma unroll
            for (int nt = 0; nt < 8; ++nt) {
                int n = nb + wn * 64 + nt * 8 + 2 * c;
                size_t i0 = ((size_t)b * M + o) * Nn + n;
                size_t i1 = i0 + (size_t)8 * Nn;
                float2 v0 = make_float2(acc[mt][nt][0] + b0, acc[mt][nt][1] + b0);
                float2 v1 = make_float2(acc[mt][nt][2] + b1, acc[mt][nt][3] + b1);
                if (resid) {
                    float2 r0 = *(const float2*)(resid + i0);
                    float2 r1 = *(const float2*)(resid + i1);
                    v0.x += r0.x; v0.y += r0.y;
                    v1.x += r1.x; v1.y += r1.y;
                }
                *(float2*)(out + i0) = v0;
                *(float2*)(out + i1) = v1;
            }
        }
    }
}

// ---------------- flash attention: max-free softmax, P in registers, 3-stage ring ----------
// round-14 body + 2 blocks/SM occupancy pin
__global__ __launch_bounds__(256, 2) void attn_mma() {
    const int b = blockIdx.z, h = blockIdx.y;
    const uint32_t* qa = g_qa + (size_t)(b * 8 + h) * 32768;
    const uint32_t* kb = g_kb + (size_t)(b * 8 + h) * 32768;
    const uint32_t* vb = g_vb + (size_t)(b * 8 + h) * 32768;

    extern __shared__ uint32_t smu[];
    const int tid = threadIdx.x, lane = tid & 31, w = tid >> 5;
    const int r = lane >> 2, c = lane & 3;
    const uint32_t sbase = smem_u32(smu);

    uint4 aq[4];
    {
        const uint32_t* qp = qa + (size_t)(blockIdx.x * 8 + w) * 512 + lane * 4;
        #pragma unroll
        for (int ks = 0; ks < 4; ++ks) aq[ks] = *(const uint4*)(qp + ks * 128);
    }

    auto stage = [&](int kt) {
        int buf = kt % 3;
        const uint32_t* kg = kb + (size_t)kt * 2048 + tid * 8;
        const uint32_t* vg = vb + (size_t)kt * 2048 + tid * 8;
        uint32_t ksm = sbase + (buf * 2048 + tid * 8) * 4;
        uint32_t vsm = sbase + (6144 + buf * 2048 + tid * 8) * 4;
        cp16(ksm,      kg);
        cp16(ksm + 16, kg + 4);
        cp16(vsm,      vg);
        cp16(vsm + 16, vg + 4);
        CP_COMMIT();
    };

    float oacc[8][4];
    #pragma unroll
    for (int j = 0; j < 8; ++j)
        #pragma unroll
        for (int i = 0; i < 4; ++i) oacc[j][i] = 0.f;
    float rs0 = 0.f, rs1 = 0.f;

    stage(0);
    stage(1);
    CP_WAIT(1);
    __syncthreads();

    for (int kt = 0; kt < 16; ++kt) {
        if (kt + 2 < 16) stage(kt + 2);

        const uint32_t* ksb = smu + (kt % 3) * 2048;
        const uint32_t* vsb = smu + 6144 + (kt % 3) * 2048;

        // S = Q K^T
        float sacc[8][4];
        #pragma unroll
        for (int j = 0; j < 8; ++j)
            #pragma unroll
            for (int i = 0; i < 4; ++i) sacc[j][i] = 0.f;
        #pragma unroll
        for (int ks = 0; ks < 4; ++ks) {
            uint2 bk[8];
            #pragma unroll
            for (int j = 0; j < 8; ++j)
                bk[j] = *(const uint2*)(ksb + ks * 512 + (j * 8 + r) * 8 + c * 2);
            #pragma unroll
            for (int j = 0; j < 8; ++j)
                mma_bf16(sacc[j], (const uint32_t*)&aq[ks], (const uint32_t*)&bk[j]);
        }

        // max-free softmax: P = exp2(S), accumulate sums, pack P for PV
        float ts0 = 0.f, ts1 = 0.f;
        uint4 pa[4];
        #pragma unroll
        for (int t = 0; t < 4; ++t) {
            float e0 = fexp2(sacc[2*t][0]);
            float e1 = fexp2(sacc[2*t][1]);
            float e2 = fexp2(sacc[2*t][2]);
            float e3 = fexp2(sacc[2*t][3]);
            float f0 = fexp2(sacc[2*t+1][0]);
            float f1 = fexp2(sacc[2*t+1][1]);
            float f2 = fexp2(sacc[2*t+1][2]);
            float f3 = fexp2(sacc[2*t+1][3]);
            ts0 += e0 + e1 + f0 + f1;
            ts1 += e2 + e3 + f2 + f3;
            pa[t] = make_uint4(pack2(e0, e1), pack2(e2, e3),
                               pack2(f0, f1), pack2(f2, f3));
        }
        rs0 += ts0;
        rs1 += ts1;

        // O += P V
        #pragma unroll
        for (int ks = 0; ks < 4; ++ks) {
            #pragma unroll
            for (int j = 0; j < 8; ++j) {
                uint2 bv = *(const uint2*)(vsb + ks * 512 + (j * 8 + r) * 8 + c * 2);
                mma_bf16(oacc[j], (const uint32_t*)&pa[ks], (const uint32_t*)&bv);
            }
        }

        CP_WAIT(1);
        __syncthreads();
    }

    // row-sum reduce across quad, normalize, transpose via smem, write bf16 b-frag
    rs0 += __shfl_xor_sync(0xffffffffu, rs0, 1);
    rs0 += __shfl_xor_sync(0xffffffffu, rs0, 2);
    rs1 += __shfl_xor_sync(0xffffffffu, rs1, 1);
    rs1 += __shfl_xor_sync(0xffffffffu, rs1, 2);
    float inv0 = 1.f / rs0, inv1 = 1.f / rs1;
    float* os = (float*)smu;   // 64 x 132 floats
    int q0 = w * 16 + r;
    #pragma unroll
    for (int j = 0; j < 8; ++j) {
        int d = j * 8 + 2 * c;
        os[d * 132 + q0]           = oacc[j][0] * inv0;
        os[(d + 1) * 132 + q0]     = oacc[j][1] * inv0;
        os[d * 132 + q0 + 8]       = oacc[j][2] * inv1;
        os[(d + 1) * 132 + q0 + 8] = oacc[j][3] * inv1;
    }
    __syncthreads();
    const int qbase = blockIdx.x * 128;
    #pragma unroll
    for (int rr = 0; rr < 8; ++rr) {
        int f = tid + rr * 256;
        int t = f & 3, nl = (f >> 2) & 127, ksl = f >> 9;
        int c0 = ksl * 16 + 2 * t;
        uint2 wv;
        wv.x = pack2(os[c0 * 132 + nl],       os[(c0 + 1) * 132 + nl]);
        wv.y = pack2(os[(c0 + 8) * 132 + nl], os[(c0 + 9) * 132 + nl]);
        *(uint2*)(g_atb + ((size_t)b * 32 + h * 4 + ksl) * 8192
                  + (size_t)(qbase + nl) * 8 + t * 2) = wv;
    }
}

// ---------------- launch ----------------
extern "C" void kernel_launch(void* const* d_in, const int* in_sizes, int n_in,
                              void* d_out, int out_size) {
    const float* x      = (const float*)d_in[0];
    const float* gamma  = (const float*)d_in[1];
    const float* beta   = (const float*)d_in[2];
    const float* w_qkv  = (const float*)d_in[3];
    const float* b_qkv  = (const float*)d_in[4];
    const float* w_proj = (const float*)d_in[5];
    const float* b_proj = (const float*)d_in[6];
    float* out = (float*)d_out;

    uint32_t *xb, *atb, *wA, *wP;
    cudaGetSymbolAddress((void**)&xb,  g_xb);
    cudaGetSymbolAddress((void**)&atb, g_atb);
    cudaGetSymbolAddress((void**)&wA,  g_wA);
    cudaGetSymbolAddress((void**)&wP,  g_wP);

    const int prep_smem = 16 * 1024 * sizeof(float);   // 64 KB (gn blocks)
    const int gemm_smem = 32768;                       // 4 stages x 8 KB
    const int attn_smem = 12288 * 4;                   // 49152 B (3-stage ring)
    cudaFuncSetAttribute(prep_kernel, cudaFuncAttributeMaxDynamicSharedMemorySize, prep_smem);
    cudaFuncSetAttribute(gemm_mma,    cudaFuncAttributeMaxDynamicSharedMemorySize, gemm_smem);
    cudaFuncSetAttribute(attn_mma,    cudaFuncAttributeMaxDynamicSharedMemorySize, attn_smem);

    prep_kernel<<<2304, 256, prep_smem>>>(w_qkv, w_proj, x, gamma, beta);
    gemm_mma<<<dim3(8, 12, 8), 256, gemm_smem>>>(wA, xb, b_qkv, nullptr, nullptr, 0, 1);
    attn_mma<<<dim3(8, NH, Bn), 256, attn_smem>>>();
    gemm_mma<<<dim3(8, 4, 8), 256, gemm_smem>>>(wP, atb, b_proj, x, out, Cc, 0);
}